// round 10
// baseline (speedup 1.0000x reference)
#include <cuda_runtime.h>
#include <cstdint>
#include <math.h>

#define T_TOT 2048
#define B_TOT 64
#define TNO   501
#define DPI   3.141592653589793

// ---------------- scratch (no allocations allowed) ----------------
__device__ float g_rk[TNO];
__device__ float g_th[B_TOT * T_TOT];
__device__ float g_nn[B_TOT * T_TOT];

// ---------------- threefry2x32 (matches jax/_src/prng.py) ----------------
__host__ __device__ __forceinline__ constexpr uint32_t rotl32(uint32_t x, int r) {
    return (x << r) | (x >> (32 - r));
}

struct U2 { uint32_t a, b; };

__host__ __device__ __forceinline__ constexpr U2 tf2x32(uint32_t k0, uint32_t k1,
                                                        uint32_t x0, uint32_t x1) {
    uint32_t k2 = k0 ^ k1 ^ 0x1BD11BDAu;
    x0 += k0; x1 += k1;
#define TFR(r) { x0 += x1; x1 = rotl32(x1, (r)) ^ x0; }
    TFR(13) TFR(15) TFR(26) TFR(6)
    x0 += k1; x1 += k2 + 1u;
    TFR(17) TFR(29) TFR(16) TFR(24)
    x0 += k2; x1 += k0 + 2u;
    TFR(13) TFR(15) TFR(26) TFR(6)
    x0 += k0; x1 += k1 + 3u;
    TFR(17) TFR(29) TFR(16) TFR(24)
    x0 += k1; x1 += k2 + 4u;
    TFR(13) TFR(15) TFR(26) TFR(6)
    x0 += k2; x1 += k0 + 5u;
#undef TFR
    return U2{x0, x1};
}

// ---------------- compile-time key chain ----------------
struct SubTab { uint32_t v[2 * T_TOT]; };

constexpr SubTab make_subtab() {
    SubTab s{};
    uint32_t k0 = 0u, k1 = 42u;
    for (int t = 0; t < T_TOT; ++t) {
        U2 nk = tf2x32(k0, k1, 0u, 0u);
        U2 sb = tf2x32(k0, k1, 0u, 1u);
        s.v[2 * t]     = sb.a;
        s.v[2 * t + 1] = sb.b;
        k0 = nk.a; k1 = nk.b;
    }
    return s;
}

__device__ constexpr SubTab g_subtab = make_subtab();

// ---------------- double-float log (abs err ~4e-10 over needed range) ----------------
__device__ __forceinline__ void log_df(float v, float& rh, float& rl) {
    int iv = __float_as_int(v);
    int e = ((iv >> 23) & 0xFF) - 127;
    float m = __int_as_float((iv & 0x007FFFFF) | 0x3F800000);
    if (m > 1.4142135f) { m *= 0.5f; e += 1; }
    float num = m - 1.0f;                              // exact (Sterbenz)
    float dh = m + 1.0f;
    float bb = dh - m;
    float dl = (m - (dh - bb)) + (1.0f - bb);
    float q  = num / dh;
    float r  = fmaf(-q, dh, num);
    r        = fmaf(-q, dl, r);
    float zl = r / dh;
    float z2 = q * q;
    float p = 0.0666666667f;
    p = fmaf(p, z2, 0.0769230769f);
    p = fmaf(p, z2, 0.0909090909f);
    p = fmaf(p, z2, 0.1111111111f);
    p = fmaf(p, z2, 0.1428571429f);
    p = fmaf(p, z2, 0.2f);
    p = fmaf(p, z2, 0.3333333333f);
    float hi = 2.0f * q;
    float lo = 2.0f * fmaf(q * z2, p, zl);
    float fe = (float)e;
    float eh = fe * 0.693145751953125f;
    float el = fe * 1.42860682e-06f;
    float s  = eh + hi;
    float b2 = s - eh;
    float er = (hi - b2) + (eh - (s - b2));
    rh = s;
    rl = er + el + lo;
}

// ---------------- compact fp64 log (abs err ~1e-15; replaces libdevice) ----------------
__device__ __forceinline__ double dlog(double v) {
    long long iv = __double_as_longlong(v);
    int e = (int)((iv >> 52) & 0x7FF) - 1023;
    double m = __longlong_as_double((iv & 0x000FFFFFFFFFFFFFULL) | 0x3FF0000000000000ULL);
    if (m > 1.4142135623730951) { m *= 0.5; e += 1; }
    double z  = (m - 1.0) / (m + 1.0);       // |z| <= 0.1716
    double z2 = z * z;
    double p = 1.0 / 21.0;
    p = fma(p, z2, 1.0 / 19.0);
    p = fma(p, z2, 1.0 / 17.0);
    p = fma(p, z2, 1.0 / 15.0);
    p = fma(p, z2, 1.0 / 13.0);
    p = fma(p, z2, 1.0 / 11.0);
    p = fma(p, z2, 1.0 / 9.0);
    p = fma(p, z2, 1.0 / 7.0);
    p = fma(p, z2, 1.0 / 5.0);
    p = fma(p, z2, 1.0 / 3.0);
    double inner = fma(2.0 * z * z2, p, 2.0 * z);
    return fma((double)e, 0.6931471805599453, inner);
}

__device__ __forceinline__ float floor_f32_of_double(double thd) {
    float T = (float)thd;
    if ((double)T > thd) {
        int ib = __float_as_int(T);
        if (T > 0.f)      ib -= 1;
        else if (T < 0.f) ib += 1;
        else              ib = (int)0x80000001;
        T = __int_as_float(ib);
    }
    return T;
}

// ---------------- fused precompute ----------------
// th[b][t] = floor_f32( logit_fp64(u) ): df fast path + cheap exact-fp64
// fallback in the ambiguity band.
__global__ void k_pre(const float* __restrict__ V, const float* __restrict__ D,
                      const float* __restrict__ w1, const float* __restrict__ b1,
                      const float* __restrict__ w2, const float* __restrict__ b2,
                      const float* __restrict__ Wr) {
    if (blockIdx.x >= 512) {
        int t = (blockIdx.x - 512) * 256 + threadIdx.x;
        if (t >= TNO) return;
        double raw = 7.5 * log(((double)t + 1.0) + 1e-7);
        float acc = 0.f;
        for (int i = 0; i < 30; ++i) {
            double phi = (0.5 * DPI) * (double)i;
            double bv;
            if (raw < phi - DPI || raw > phi + DPI) bv = 0.0;
            else bv = 0.5 * cos(raw - phi) + 0.5;
            acc = fmaf((float)bv, Wr[i], acc);
        }
        g_rk[500 - t] = acc;   // jnp.flip
        return;
    }

    int tid = blockIdx.x * 256 + threadIdx.x;   // b*T + t layout
    int b = tid >> 11;
    int t = tid & (T_TOT - 1);

    uint32_t s0 = g_subtab.v[2 * t];
    uint32_t s1 = g_subtab.v[2 * t + 1];
    U2 o = tf2x32(s0, s1, 0u, (uint32_t)b);
    uint32_t bits = o.a ^ o.b;
    uint32_t kb = bits >> 9;                       // u = kb * 2^-23, exact
    float th;
    if (kb == 0u) {
        th = __int_as_float(0xFF800000);           // -inf: always spike
    } else {
        float u = __uint_as_float(kb | 0x3f800000u) - 1.0f;
        float w = 1.0f - u;                        // exact (multiples of 2^-23)
        float luh, lul, lwh, lwl;
        log_df(u, luh, lul);
        log_df(w, lwh, lwl);
        // df subtraction (TwoSum on highs)
        float s  = luh - lwh;
        float bb = s - luh;
        float er = (-lwh - bb) + (luh - (s - bb));
        float lo = er + (lul - lwl);
        float H = s + lo;
        float L = lo - (H - s);
        if (L < 0.0f) {                            // floor: step down one ulp
            int ib = __float_as_int(H);
            if (H > 0.0f)      ib -= 1;
            else if (H < 0.0f) ib += 1;
            else               ib = (int)0x80000001;
            H = __int_as_float(ib);
        }
        // ambiguity check: true thd must lie strictly inside (H, nextup(H))
        float dist = (s - H) + lo;                 // thd - H (df)
        int ih = __float_as_int(H);
        float Hn = __int_as_float((H > 0.f) ? ih + 1 : ((H < 0.f) ? ih - 1 : 1));
        float width = Hn - H;
        float eps = 1e-9f + 5e-10f * fabsf(H);
        if (!(dist > eps && (width - dist) > eps)) {
            double ud = (double)u;
            double thd = dlog(ud) - dlog(1.0 - ud);   // exact-enough fp64 (err ~1e-15)
            H = floor_f32_of_double(thd);
        }
        th = H;
    }
    g_th[tid] = th;

    // pointwise tanh-MLP logits (identical math to passing rounds)
    float v = V[tid], d = D[tid];
    float acc = 0.f;
    #pragma unroll
    for (int h = 0; h < 5; ++h) {
        float s = fmaf(w1[2 * h + 1], d, w1[2 * h + 0] * v) + b1[h];
        float hh = tanhf(s);
        acc = (h == 0) ? w2[0] * hh : fmaf(w2[h], hh, acc);
    }
    g_nn[tid] = acc + b2[0];
}

// ---------------- autoregressive loop: 3 warps per batch ----------------
// warp0: serial chain. d=1..4 in registers; d=5..132 via pair-combined scatter
//        (lane-owned addresses; cross-pair reuse ordered by per-warp in-order
//        MIO + compiler fence — WARPSYNC eliminated).
// warps 1,2: (a) materialize S for block bk-1 from (x > th) [bit-identical to
//        warp0's FSETP], helpers-only bar; (b) race-free far gather d=133..501.
#define AN_LEN 2208
#define FB_LEN 2176
#define TH_LEN 2056
#define SPAD   512
#define S_LEN  (SPAD + T_TOT)
#define RK_LEN 512

__global__ void __launch_bounds__(96, 1) k_main(float* __restrict__ out) {
    __shared__ float An[AN_LEN];      // init = nn (j<2048) else 0; near accum
    __shared__ float FarB[FB_LEN];
    __shared__ float th_sh[TH_LEN];
    __shared__ float x_sh[T_TOT];
    __shared__ float S_arr[S_LEN];    // 512-zero prefix, then spikes (helper-written)
    __shared__ float rk_sh[RK_LEN];

    const int b = blockIdx.x;
    const int tid = threadIdx.x;
    const int wid = tid >> 5;
    const int lane = tid & 31;

    // ---- init ----
    {
        const float4* nn4 = reinterpret_cast<const float4*>(g_nn + b * T_TOT);
        const float4* th4 = reinterpret_cast<const float4*>(g_th + b * T_TOT);
        float4* An4 = reinterpret_cast<float4*>(An);
        float4* Th4 = reinterpret_cast<float4*>(th_sh);
        for (int i = tid; i < T_TOT / 4; i += 96) { An4[i] = nn4[i]; Th4[i] = th4[i]; }
    }
    for (int i = T_TOT + tid; i < AN_LEN; i += 96) An[i] = 0.f;
    for (int i = T_TOT + tid; i < TH_LEN; i += 96) th_sh[i] = 0.f;
    for (int i = tid; i < FB_LEN; i += 96) FarB[i] = 0.f;
    for (int i = tid; i < SPAD; i += 96) S_arr[i] = 0.f;   // zero prefix only
    for (int i = tid; i < RK_LEN; i += 96) rk_sh[i] = (i < TNO) ? g_rk[i] : 0.f;
    __syncthreads();

    if (wid == 0) {
        // ---- serial warp ----
        const float W1 = rk_sh[500], W2 = rk_sh[499], W3 = rk_sh[498], W4 = rk_sh[497];
        const float wA0 = rk_sh[496 - lane];
        const float wA1 = rk_sh[464 - lane];
        const float wA2 = rk_sh[432 - lane];
        const float wA3 = rk_sh[400 - lane];
        const float wB0 = (lane == 0) ? 0.f : rk_sh[497 - lane];
        const float wB1 = rk_sh[465 - lane];
        const float wB2 = rk_sh[433 - lane];
        const float wB3 = rk_sh[401 - lane];
        const float wX  = rk_sh[369];          // j = t+133, d1 = 132 (lane 0 only)

        // history at pair (t,t+1) entry: s1=s_{t-1}, s2=s_{t-2}, s3=s_{t-3}
        float s1 = 0.f, s2 = 0.f, s3 = 0.f;
        float preA  = An[0] + FarB[0];
        float baseB = An[1] + FarB[1];
        float thA = th_sh[0], thB = th_sh[1];
        int t = 0;

        for (int bk = 0; bk < 32; ++bk) {
            #pragma unroll 4
            for (int i = 0; i < 32; ++i) {
                // step t
                float x0  = fmaf(s1, W1, preA);
                float sp0 = (x0 > thA) ? 1.f : 0.f;
                x_sh[t] = x0;
                float anC = An[t + 2], fbC = FarB[t + 2];
                thA = th_sh[t + 2];
                // step t+1
                float preB = fmaf(s1, W2, fmaf(s2, W3, fmaf(s3, W4, baseB)));
                float x1  = fmaf(sp0, W1, preB);
                float sp1 = (x1 > thB) ? 1.f : 0.f;
                x_sh[t + 1] = x1;
                float anD = An[t + 3], fbD = FarB[t + 3];
                thB = th_sh[t + 3];
                // pair-combined scatter: lane-owned addresses only
                float* an = An + t + 5 + lane;
                an[0]  += fmaf(sp0, wA0, sp1 * wB0);
                an[32] += fmaf(sp0, wA1, sp1 * wB1);
                an[64] += fmaf(sp0, wA2, sp1 * wB2);
                an[96] += fmaf(sp0, wA3, sp1 * wB3);
                if (lane == 0) an[128] += sp1 * wX;
                // carries for next pair (step t+2: d=2 sp0, d=3 s1, d=4 s2)
                preA  = fmaf(sp0, W2, fmaf(s1, W3, fmaf(s2, W4, anC + fbC)));
                baseB = anD + fbD;
                s3 = s1; s2 = sp0; s1 = sp1;
                t += 2;
                asm volatile("" ::: "memory");   // compiler fence; same-warp MIO is in-order
            }
            asm volatile("bar.sync 0, 96;" ::: "memory");
        }
    } else {
        // ---- helper warps ----
        const int j0 = 66 + (wid - 1) * 32 + lane;
        for (int bk = 0; bk < 32; ++bk) {
            // (a) materialize S for block bk-1 (bit-identical compare to warp0)
            if (bk >= 1) {
                int js = 64 * (bk - 1) + (wid - 1) * 32 + lane;
                S_arr[SPAD + js] = (x_sh[js] > th_sh[js]) ? 1.f : 0.f;
            }
            asm volatile("bar.sync 1, 64;" ::: "memory");   // helpers only
            // (b) far gather, single-owner write
            int j = 64 * bk + j0;
            const float* sp = S_arr + (SPAD + j - 501);
            float a0 = 0.f, a1 = 0.f, a2 = 0.f;
            #pragma unroll 4
            for (int m = 0; m < 369; m += 3) {
                a0 = fmaf(sp[m],     rk_sh[m],     a0);
                a1 = fmaf(sp[m + 1], rk_sh[m + 1], a1);
                a2 = fmaf(sp[m + 2], rk_sh[m + 2], a2);
            }
            FarB[j] = a0 + a1 + a2;
            asm volatile("bar.sync 0, 96;" ::: "memory");
        }
    }

    // ---- parallel epilogue: P = sigmoid(x), S = (x > th) (bit-identical) ----
    float* Sout = out + b * T_TOT;
    float* Pout = out + B_TOT * T_TOT + b * T_TOT;
    for (int i = tid; i < T_TOT; i += 96) {
        float x = x_sh[i];
        Pout[i] = 1.0f / (1.0f + expf(-x));
        Sout[i] = (x > th_sh[i]) ? 1.f : 0.f;
    }
}

// ---------------- launch ----------------
extern "C" void kernel_launch(void* const* d_in, const int* in_sizes, int n_in,
                              void* d_out, int out_size) {
    const float* V  = (const float*)d_in[0];
    const float* D  = (const float*)d_in[1];
    const float* w1 = (const float*)d_in[2];
    const float* b1 = (const float*)d_in[3];
    const float* w2 = (const float*)d_in[4];
    const float* b2 = (const float*)d_in[5];
    const float* Wr = (const float*)d_in[6];
    float* out = (float*)d_out;

    k_pre<<<514, 256>>>(V, D, w1, b1, w2, b2, Wr);
    k_main<<<B_TOT, 96>>>(out);
}

// round 11
// speedup vs baseline: 1.6964x; 1.6964x over previous
#include <cuda_runtime.h>
#include <cstdint>
#include <math.h>

#define T_TOT 2048
#define B_TOT 64
#define TNO   501
#define DPI   3.141592653589793

// ---------------- scratch (no allocations allowed) ----------------
__device__ float g_rk[TNO];
__device__ float g_th[B_TOT * T_TOT];
__device__ float g_nn[B_TOT * T_TOT];

// ---------------- threefry2x32 (matches jax/_src/prng.py) ----------------
__host__ __device__ __forceinline__ constexpr uint32_t rotl32(uint32_t x, int r) {
    return (x << r) | (x >> (32 - r));
}

struct U2 { uint32_t a, b; };

__host__ __device__ __forceinline__ constexpr U2 tf2x32(uint32_t k0, uint32_t k1,
                                                        uint32_t x0, uint32_t x1) {
    uint32_t k2 = k0 ^ k1 ^ 0x1BD11BDAu;
    x0 += k0; x1 += k1;
#define TFR(r) { x0 += x1; x1 = rotl32(x1, (r)) ^ x0; }
    TFR(13) TFR(15) TFR(26) TFR(6)
    x0 += k1; x1 += k2 + 1u;
    TFR(17) TFR(29) TFR(16) TFR(24)
    x0 += k2; x1 += k0 + 2u;
    TFR(13) TFR(15) TFR(26) TFR(6)
    x0 += k0; x1 += k1 + 3u;
    TFR(17) TFR(29) TFR(16) TFR(24)
    x0 += k1; x1 += k2 + 4u;
    TFR(13) TFR(15) TFR(26) TFR(6)
    x0 += k2; x1 += k0 + 5u;
#undef TFR
    return U2{x0, x1};
}

// ---------------- compile-time key chain ----------------
struct SubTab { uint32_t v[2 * T_TOT]; };

constexpr SubTab make_subtab() {
    SubTab s{};
    uint32_t k0 = 0u, k1 = 42u;
    for (int t = 0; t < T_TOT; ++t) {
        U2 nk = tf2x32(k0, k1, 0u, 0u);
        U2 sb = tf2x32(k0, k1, 0u, 1u);
        s.v[2 * t]     = sb.a;
        s.v[2 * t + 1] = sb.b;
        k0 = nk.a; k1 = nk.b;
    }
    return s;
}

__device__ constexpr SubTab g_subtab = make_subtab();

// ---------------- double-float log (abs err ~1e-11 after cubic fix) ----------------
__device__ __forceinline__ void log_df(float v, float& rh, float& rl) {
    int iv = __float_as_int(v);
    int e = ((iv >> 23) & 0xFF) - 127;
    float m = __int_as_float((iv & 0x007FFFFF) | 0x3F800000);
    if (m > 1.4142135f) { m *= 0.5f; e += 1; }
    float num = m - 1.0f;                              // exact (Sterbenz)
    float dh = m + 1.0f;
    float bb = dh - m;
    float dl = (m - (dh - bb)) + (1.0f - bb);
    float q  = num / dh;
    float r  = fmaf(-q, dh, num);
    r        = fmaf(-q, dl, r);
    float zl = r / dh;                                 // z = q + zl (df)
    float z2 = q * q;
    float p = 0.0666666667f;
    p = fmaf(p, z2, 0.0769230769f);
    p = fmaf(p, z2, 0.0909090909f);
    p = fmaf(p, z2, 0.1111111111f);
    p = fmaf(p, z2, 0.1428571429f);
    p = fmaf(p, z2, 0.2f);
    p = fmaf(p, z2, 0.3333333333f);
    float hi = 2.0f * q;
    // zl correction through the series derivative (1 + z^2): kills the ~6e-10
    // cubic-term error from using q instead of (q+zl) in z2.
    float corr = fmaf(zl, z2, zl);
    float lo = 2.0f * fmaf(q * z2, p, corr);
    float fe = (float)e;
    float eh = fe * 0.693145751953125f;
    float el = fe * 1.42860682e-06f;
    float s  = eh + hi;
    float b2 = s - eh;
    float er = (hi - b2) + (eh - (s - b2));
    rh = s;
    rl = er + el + lo;
}

// ---------------- compact fp64 log (abs err ~1e-15; replaces libdevice) ----------------
__device__ __forceinline__ double dlog(double v) {
    long long iv = __double_as_longlong(v);
    int e = (int)((iv >> 52) & 0x7FF) - 1023;
    double m = __longlong_as_double((iv & 0x000FFFFFFFFFFFFFULL) | 0x3FF0000000000000ULL);
    if (m > 1.4142135623730951) { m *= 0.5; e += 1; }
    double z  = (m - 1.0) / (m + 1.0);       // |z| <= 0.1716
    double z2 = z * z;
    double p = 1.0 / 21.0;
    p = fma(p, z2, 1.0 / 19.0);
    p = fma(p, z2, 1.0 / 17.0);
    p = fma(p, z2, 1.0 / 15.0);
    p = fma(p, z2, 1.0 / 13.0);
    p = fma(p, z2, 1.0 / 11.0);
    p = fma(p, z2, 1.0 / 9.0);
    p = fma(p, z2, 1.0 / 7.0);
    p = fma(p, z2, 1.0 / 5.0);
    p = fma(p, z2, 1.0 / 3.0);
    double inner = fma(2.0 * z * z2, p, 2.0 * z);
    return fma((double)e, 0.6931471805599453, inner);
}

__device__ __forceinline__ float floor_f32_of_double(double thd) {
    float T = (float)thd;
    if ((double)T > thd) {
        int ib = __float_as_int(T);
        if (T > 0.f)      ib -= 1;
        else if (T < 0.f) ib += 1;
        else              ib = (int)0x80000001;
        T = __int_as_float(ib);
    }
    return T;
}

// ---------------- fused precompute ----------------
// th[b][t] = floor_f32( logit_fp64(u) ): df fast path + rare fp64 fallback
// (logit via single dlog(u/(1-u))). Both paths produce the same correct floor.
__global__ void k_pre(const float* __restrict__ V, const float* __restrict__ D,
                      const float* __restrict__ w1, const float* __restrict__ b1,
                      const float* __restrict__ w2, const float* __restrict__ b2,
                      const float* __restrict__ Wr) {
    if (blockIdx.x >= 512) {
        int t = (blockIdx.x - 512) * 256 + threadIdx.x;
        if (t >= TNO) return;
        double raw = 7.5 * log(((double)t + 1.0) + 1e-7);
        float acc = 0.f;
        for (int i = 0; i < 30; ++i) {
            double phi = (0.5 * DPI) * (double)i;
            double bv;
            if (raw < phi - DPI || raw > phi + DPI) bv = 0.0;
            else bv = 0.5 * cos(raw - phi) + 0.5;
            acc = fmaf((float)bv, Wr[i], acc);
        }
        g_rk[500 - t] = acc;   // jnp.flip
        return;
    }

    int tid = blockIdx.x * 256 + threadIdx.x;   // b*T + t layout
    int b = tid >> 11;
    int t = tid & (T_TOT - 1);

    uint32_t s0 = g_subtab.v[2 * t];
    uint32_t s1 = g_subtab.v[2 * t + 1];
    U2 o = tf2x32(s0, s1, 0u, (uint32_t)b);
    uint32_t bits = o.a ^ o.b;
    uint32_t kb = bits >> 9;                       // u = kb * 2^-23, exact
    float th;
    if (kb == 0u) {
        th = __int_as_float(0xFF800000);           // -inf: always spike
    } else {
        float u = __uint_as_float(kb | 0x3f800000u) - 1.0f;
        float w = 1.0f - u;                        // exact (multiples of 2^-23)
        float luh, lul, lwh, lwl;
        log_df(u, luh, lul);
        log_df(w, lwh, lwl);
        // df subtraction (TwoSum on highs)
        float s  = luh - lwh;
        float bb = s - luh;
        float er = (-lwh - bb) + (luh - (s - bb));
        float lo = er + (lul - lwl);
        float H = s + lo;
        float L = lo - (H - s);
        if (L < 0.0f) {                            // floor: step down one ulp
            int ib = __float_as_int(H);
            if (H > 0.0f)      ib -= 1;
            else if (H < 0.0f) ib += 1;
            else               ib = (int)0x80000001;
            H = __int_as_float(ib);
        }
        // ambiguity check: true thd must lie strictly inside (H, nextup(H))
        float dist = (s - H) + lo;                 // thd - H (df)
        int ih = __float_as_int(H);
        float Hn = __int_as_float((H > 0.f) ? ih + 1 : ((H < 0.f) ? ih - 1 : 1));
        float width = Hn - H;
        float eps = 2e-10f + 2e-11f * fabsf(H);    // >=10x df err after cubic fix
        if (!(dist > eps && (width - dist) > eps)) {
            double ud = (double)u;
            double thd = dlog(ud / (1.0 - ud));    // single fp64 log (err ~1e-15)
            H = floor_f32_of_double(thd);
        }
        th = H;
    }
    g_th[tid] = th;

    // pointwise tanh-MLP logits (identical math to passing rounds)
    float v = V[tid], d = D[tid];
    float acc = 0.f;
    #pragma unroll
    for (int h = 0; h < 5; ++h) {
        float s = fmaf(w1[2 * h + 1], d, w1[2 * h + 0] * v) + b1[h];
        float hh = tanhf(s);
        acc = (h == 0) ? w2[0] * hh : fmaf(w2[h], hh, acc);
    }
    g_nn[tid] = acc + b2[0];
}

// ---------------- autoregressive loop: 3 warps per batch ----------------
// warp0: serial chain. d=1..4 in registers; d=5..132 via pair-combined scatter
//        (lane-owned addresses; cross-pair reuse ordered by per-warp in-order
//        MIO + compiler fence).
// warps 1,2: (a) materialize S for block bk-1 from (x > th) [bit-identical to
//        warp0's FSETP], helpers-only bar; (b) race-free far gather d=133..501.
#define AN_LEN 2208
#define FB_LEN 2176
#define TH_LEN 2056
#define SPAD   512
#define S_LEN  (SPAD + T_TOT)
#define RK_LEN 512

__global__ void __launch_bounds__(96, 1) k_main(float* __restrict__ out) {
    __shared__ float An[AN_LEN];      // init = nn (j<2048) else 0; near accum
    __shared__ float FarB[FB_LEN];
    __shared__ float th_sh[TH_LEN];
    __shared__ float x_sh[T_TOT];
    __shared__ float S_arr[S_LEN];    // 512-zero prefix, then spikes (helper-written)
    __shared__ float rk_sh[RK_LEN];

    const int b = blockIdx.x;
    const int tid = threadIdx.x;
    const int wid = tid >> 5;
    const int lane = tid & 31;

    // ---- init ----
    {
        const float4* nn4 = reinterpret_cast<const float4*>(g_nn + b * T_TOT);
        const float4* th4 = reinterpret_cast<const float4*>(g_th + b * T_TOT);
        float4* An4 = reinterpret_cast<float4*>(An);
        float4* Th4 = reinterpret_cast<float4*>(th_sh);
        for (int i = tid; i < T_TOT / 4; i += 96) { An4[i] = nn4[i]; Th4[i] = th4[i]; }
    }
    for (int i = T_TOT + tid; i < AN_LEN; i += 96) An[i] = 0.f;
    for (int i = T_TOT + tid; i < TH_LEN; i += 96) th_sh[i] = 0.f;
    for (int i = tid; i < FB_LEN; i += 96) FarB[i] = 0.f;
    for (int i = tid; i < SPAD; i += 96) S_arr[i] = 0.f;   // zero prefix only
    for (int i = tid; i < RK_LEN; i += 96) rk_sh[i] = (i < TNO) ? g_rk[i] : 0.f;
    __syncthreads();

    if (wid == 0) {
        // ---- serial warp ----
        const float W1 = rk_sh[500], W2 = rk_sh[499], W3 = rk_sh[498], W4 = rk_sh[497];
        const float wA0 = rk_sh[496 - lane];
        const float wA1 = rk_sh[464 - lane];
        const float wA2 = rk_sh[432 - lane];
        const float wA3 = rk_sh[400 - lane];
        const float wB0 = (lane == 0) ? 0.f : rk_sh[497 - lane];
        const float wB1 = rk_sh[465 - lane];
        const float wB2 = rk_sh[433 - lane];
        const float wB3 = rk_sh[401 - lane];
        const float wX  = rk_sh[369];          // j = t+133, d1 = 132 (lane 0 only)

        // history at pair (t,t+1) entry: s1=s_{t-1}, s2=s_{t-2}, s3=s_{t-3}
        float s1 = 0.f, s2 = 0.f, s3 = 0.f;
        float preA  = An[0] + FarB[0];
        float baseB = An[1] + FarB[1];
        float thA = th_sh[0], thB = th_sh[1];
        int t = 0;

        for (int bk = 0; bk < 32; ++bk) {
            #pragma unroll 2
            for (int i = 0; i < 32; ++i) {
                // step t
                float x0  = fmaf(s1, W1, preA);
                float sp0 = (x0 > thA) ? 1.f : 0.f;
                x_sh[t] = x0;
                float anC = An[t + 2], fbC = FarB[t + 2];
                thA = th_sh[t + 2];
                // step t+1
                float preB = fmaf(s1, W2, fmaf(s2, W3, fmaf(s3, W4, baseB)));
                float x1  = fmaf(sp0, W1, preB);
                float sp1 = (x1 > thB) ? 1.f : 0.f;
                x_sh[t + 1] = x1;
                float anD = An[t + 3], fbD = FarB[t + 3];
                thB = th_sh[t + 3];
                // pair-combined scatter: lane-owned addresses only
                float* an = An + t + 5 + lane;
                an[0]  += fmaf(sp0, wA0, sp1 * wB0);
                an[32] += fmaf(sp0, wA1, sp1 * wB1);
                an[64] += fmaf(sp0, wA2, sp1 * wB2);
                an[96] += fmaf(sp0, wA3, sp1 * wB3);
                if (lane == 0) an[128] += sp1 * wX;
                // carries for next pair (step t+2: d=2 sp0, d=3 s1, d=4 s2)
                preA  = fmaf(sp0, W2, fmaf(s1, W3, fmaf(s2, W4, anC + fbC)));
                baseB = anD + fbD;
                s3 = s1; s2 = sp0; s1 = sp1;
                t += 2;
                asm volatile("" ::: "memory");   // compiler fence; same-warp MIO is in-order
            }
            asm volatile("bar.sync 0, 96;" ::: "memory");
        }
    } else {
        // ---- helper warps ----
        const int j0 = 66 + (wid - 1) * 32 + lane;
        for (int bk = 0; bk < 32; ++bk) {
            // (a) materialize S for block bk-1 (bit-identical compare to warp0)
            if (bk >= 1) {
                int js = 64 * (bk - 1) + (wid - 1) * 32 + lane;
                S_arr[SPAD + js] = (x_sh[js] > th_sh[js]) ? 1.f : 0.f;
            }
            asm volatile("bar.sync 1, 64;" ::: "memory");   // helpers only
            // (b) far gather, single-owner write
            int j = 64 * bk + j0;
            const float* sp = S_arr + (SPAD + j - 501);
            float a0 = 0.f, a1 = 0.f, a2 = 0.f;
            #pragma unroll 4
            for (int m = 0; m < 369; m += 3) {
                a0 = fmaf(sp[m],     rk_sh[m],     a0);
                a1 = fmaf(sp[m + 1], rk_sh[m + 1], a1);
                a2 = fmaf(sp[m + 2], rk_sh[m + 2], a2);
            }
            FarB[j] = a0 + a1 + a2;
            asm volatile("bar.sync 0, 96;" ::: "memory");
        }
    }

    // ---- parallel epilogue: P = sigmoid(x), S = (x > th) (bit-identical) ----
    float* Sout = out + b * T_TOT;
    float* Pout = out + B_TOT * T_TOT + b * T_TOT;
    for (int i = tid; i < T_TOT; i += 96) {
        float x = x_sh[i];
        Pout[i] = 1.0f / (1.0f + expf(-x));
        Sout[i] = (x > th_sh[i]) ? 1.f : 0.f;
    }
}

// ---------------- launch ----------------
extern "C" void kernel_launch(void* const* d_in, const int* in_sizes, int n_in,
                              void* d_out, int out_size) {
    const float* V  = (const float*)d_in[0];
    const float* D  = (const float*)d_in[1];
    const float* w1 = (const float*)d_in[2];
    const float* b1 = (const float*)d_in[3];
    const float* w2 = (const float*)d_in[4];
    const float* b2 = (const float*)d_in[5];
    const float* Wr = (const float*)d_in[6];
    float* out = (float*)d_out;

    k_pre<<<514, 256>>>(V, D, w1, b1, w2, b2, Wr);
    k_main<<<B_TOT, 96>>>(out);
}

// round 14
// speedup vs baseline: 1.8426x; 1.0861x over previous
#include <cuda_runtime.h>
#include <cstdint>
#include <math.h>

#define T_TOT 2048
#define B_TOT 64
#define TNO   501
#define DPI   3.141592653589793

// ---------------- scratch (no allocations allowed) ----------------
__device__ float g_rk[TNO];
__device__ float g_th[B_TOT * T_TOT];
__device__ float g_nn[B_TOT * T_TOT];

// ---------------- threefry2x32 (matches jax/_src/prng.py) ----------------
__host__ __device__ __forceinline__ constexpr uint32_t rotl32(uint32_t x, int r) {
    return (x << r) | (x >> (32 - r));
}

struct U2 { uint32_t a, b; };

__host__ __device__ __forceinline__ constexpr U2 tf2x32(uint32_t k0, uint32_t k1,
                                                        uint32_t x0, uint32_t x1) {
    uint32_t k2 = k0 ^ k1 ^ 0x1BD11BDAu;
    x0 += k0; x1 += k1;
#define TFR(r) { x0 += x1; x1 = rotl32(x1, (r)) ^ x0; }
    TFR(13) TFR(15) TFR(26) TFR(6)
    x0 += k1; x1 += k2 + 1u;
    TFR(17) TFR(29) TFR(16) TFR(24)
    x0 += k2; x1 += k0 + 2u;
    TFR(13) TFR(15) TFR(26) TFR(6)
    x0 += k0; x1 += k1 + 3u;
    TFR(17) TFR(29) TFR(16) TFR(24)
    x0 += k1; x1 += k2 + 4u;
    TFR(13) TFR(15) TFR(26) TFR(6)
    x0 += k2; x1 += k0 + 5u;
#undef TFR
    return U2{x0, x1};
}

// ---------------- compile-time key chain ----------------
struct SubTab { uint32_t v[2 * T_TOT]; };

constexpr SubTab make_subtab() {
    SubTab s{};
    uint32_t k0 = 0u, k1 = 42u;
    for (int t = 0; t < T_TOT; ++t) {
        U2 nk = tf2x32(k0, k1, 0u, 0u);
        U2 sb = tf2x32(k0, k1, 0u, 1u);
        s.v[2 * t]     = sb.a;
        s.v[2 * t + 1] = sb.b;
        k0 = nk.a; k1 = nk.b;
    }
    return s;
}

__device__ constexpr SubTab g_subtab = make_subtab();

// ---------------- double-float log (abs err ~1e-11 after cubic fix) ----------------
__device__ __forceinline__ void log_df(float v, float& rh, float& rl) {
    int iv = __float_as_int(v);
    int e = ((iv >> 23) & 0xFF) - 127;
    float m = __int_as_float((iv & 0x007FFFFF) | 0x3F800000);
    if (m > 1.4142135f) { m *= 0.5f; e += 1; }
    float num = m - 1.0f;                              // exact (Sterbenz)
    float dh = m + 1.0f;
    float bb = dh - m;
    float dl = (m - (dh - bb)) + (1.0f - bb);
    float q  = num / dh;
    float r  = fmaf(-q, dh, num);
    r        = fmaf(-q, dl, r);
    float zl = r / dh;                                 // z = q + zl (df)
    float z2 = q * q;
    float p = 0.0666666667f;
    p = fmaf(p, z2, 0.0769230769f);
    p = fmaf(p, z2, 0.0909090909f);
    p = fmaf(p, z2, 0.1111111111f);
    p = fmaf(p, z2, 0.1428571429f);
    p = fmaf(p, z2, 0.2f);
    p = fmaf(p, z2, 0.3333333333f);
    float hi = 2.0f * q;
    float corr = fmaf(zl, z2, zl);
    float lo = 2.0f * fmaf(q * z2, p, corr);
    float fe = (float)e;
    float eh = fe * 0.693145751953125f;
    float el = fe * 1.42860682e-06f;
    float s  = eh + hi;
    float b2 = s - eh;
    float er = (hi - b2) + (eh - (s - b2));
    rh = s;
    rl = er + el + lo;
}

// ---------------- compact fp64 log (abs err ~1e-15) ----------------
__device__ __forceinline__ double dlog(double v) {
    long long iv = __double_as_longlong(v);
    int e = (int)((iv >> 52) & 0x7FF) - 1023;
    double m = __longlong_as_double((iv & 0x000FFFFFFFFFFFFFULL) | 0x3FF0000000000000ULL);
    if (m > 1.4142135623730951) { m *= 0.5; e += 1; }
    double z  = (m - 1.0) / (m + 1.0);
    double z2 = z * z;
    double p = 1.0 / 21.0;
    p = fma(p, z2, 1.0 / 19.0);
    p = fma(p, z2, 1.0 / 17.0);
    p = fma(p, z2, 1.0 / 15.0);
    p = fma(p, z2, 1.0 / 13.0);
    p = fma(p, z2, 1.0 / 11.0);
    p = fma(p, z2, 1.0 / 9.0);
    p = fma(p, z2, 1.0 / 7.0);
    p = fma(p, z2, 1.0 / 5.0);
    p = fma(p, z2, 1.0 / 3.0);
    double inner = fma(2.0 * z * z2, p, 2.0 * z);
    return fma((double)e, 0.6931471805599453, inner);
}

__device__ __forceinline__ float floor_f32_of_double(double thd) {
    float T = (float)thd;
    if ((double)T > thd) {
        int ib = __float_as_int(T);
        if (T > 0.f)      ib -= 1;
        else if (T < 0.f) ib += 1;
        else              ib = (int)0x80000001;
        T = __int_as_float(ib);
    }
    return T;
}

// ---------------- fused precompute (unchanged from passing R11) ----------------
__global__ void k_pre(const float* __restrict__ V, const float* __restrict__ D,
                      const float* __restrict__ w1, const float* __restrict__ b1,
                      const float* __restrict__ w2, const float* __restrict__ b2,
                      const float* __restrict__ Wr) {
    if (blockIdx.x >= 512) {
        int t = (blockIdx.x - 512) * 256 + threadIdx.x;
        if (t >= TNO) return;
        double raw = 7.5 * log(((double)t + 1.0) + 1e-7);
        float acc = 0.f;
        for (int i = 0; i < 30; ++i) {
            double phi = (0.5 * DPI) * (double)i;
            double bv;
            if (raw < phi - DPI || raw > phi + DPI) bv = 0.0;
            else bv = 0.5 * cos(raw - phi) + 0.5;
            acc = fmaf((float)bv, Wr[i], acc);
        }
        g_rk[500 - t] = acc;   // jnp.flip
        return;
    }

    int tid = blockIdx.x * 256 + threadIdx.x;   // b*T + t layout
    int b = tid >> 11;
    int t = tid & (T_TOT - 1);

    uint32_t s0 = g_subtab.v[2 * t];
    uint32_t s1 = g_subtab.v[2 * t + 1];
    U2 o = tf2x32(s0, s1, 0u, (uint32_t)b);
    uint32_t bits = o.a ^ o.b;
    uint32_t kb = bits >> 9;                       // u = kb * 2^-23, exact
    float th;
    if (kb == 0u) {
        th = __int_as_float(0xFF800000);           // -inf: always spike
    } else {
        float u = __uint_as_float(kb | 0x3f800000u) - 1.0f;
        float w = 1.0f - u;                        // exact
        float luh, lul, lwh, lwl;
        log_df(u, luh, lul);
        log_df(w, lwh, lwl);
        float s  = luh - lwh;
        float bb = s - luh;
        float er = (-lwh - bb) + (luh - (s - bb));
        float lo = er + (lul - lwl);
        float H = s + lo;
        float L = lo - (H - s);
        if (L < 0.0f) {
            int ib = __float_as_int(H);
            if (H > 0.0f)      ib -= 1;
            else if (H < 0.0f) ib += 1;
            else               ib = (int)0x80000001;
            H = __int_as_float(ib);
        }
        float dist = (s - H) + lo;
        int ih = __float_as_int(H);
        float Hn = __int_as_float((H > 0.f) ? ih + 1 : ((H < 0.f) ? ih - 1 : 1));
        float width = Hn - H;
        float eps = 2e-10f + 2e-11f * fabsf(H);
        if (!(dist > eps && (width - dist) > eps)) {
            double ud = (double)u;
            double thd = dlog(ud / (1.0 - ud));
            H = floor_f32_of_double(thd);
        }
        th = H;
    }
    g_th[tid] = th;

    float v = V[tid], d = D[tid];
    float acc = 0.f;
    #pragma unroll
    for (int h = 0; h < 5; ++h) {
        float s = fmaf(w1[2 * h + 1], d, w1[2 * h + 0] * v) + b1[h];
        float hh = tanhf(s);
        acc = (h == 0) ? w2[0] * hh : fmaf(w2[h], hh, acc);
    }
    g_nn[tid] = acc + b2[0];
}

// ---------------- autoregressive loop: 3 warps per batch, 16-step phases ----------------
// warp0: serial chain; d=1..4 regs, d=5..36 single-chunk scatter (+lane0 patch).
// warps 1,2: per phase p: (a) redundantly materialize S for block p-1,
//   (b) gather Far[j] = sum_{d=37..501} S[j-d]*rk[501-d] (m = 0..464 ONLY —
//   entries m=465..467 masked to zero; they alias taps d=34..36 which warp0
//   owns, and double-counting them was the R13 bug), offset +18 from warp0's
//   prefetch window, register-resident weights, butterfly-reduce, owner write.
#define AN_LEN 2112
#define FB_LEN 2080
#define TH_LEN 2056
#define SPAD   512
#define S_LEN  (SPAD + T_TOT)
#define RK_LEN 512

__global__ void __launch_bounds__(96, 1) k_main(float* __restrict__ out) {
    __shared__ float An[AN_LEN];      // init = nn (j<2048) else 0; near accum d<=36
    __shared__ float Far[FB_LEN];     // d>=37 background (helper-gathered)
    __shared__ float th_sh[TH_LEN];
    __shared__ float x_sh[T_TOT];
    __shared__ float S_arr[S_LEN];    // 512-zero prefix, then spikes
    __shared__ float rk_sh[RK_LEN];

    const int b = blockIdx.x;
    const int tid = threadIdx.x;
    const int wid = tid >> 5;
    const int lane = tid & 31;

    // ---- init ----
    {
        const float4* nn4 = reinterpret_cast<const float4*>(g_nn + b * T_TOT);
        const float4* th4 = reinterpret_cast<const float4*>(g_th + b * T_TOT);
        float4* An4 = reinterpret_cast<float4*>(An);
        float4* Th4 = reinterpret_cast<float4*>(th_sh);
        for (int i = tid; i < T_TOT / 4; i += 96) { An4[i] = nn4[i]; Th4[i] = th4[i]; }
    }
    for (int i = T_TOT + tid; i < AN_LEN; i += 96) An[i] = 0.f;
    for (int i = T_TOT + tid; i < TH_LEN; i += 96) th_sh[i] = 0.f;
    for (int i = tid; i < FB_LEN; i += 96) Far[i] = 0.f;
    for (int i = tid; i < SPAD; i += 96) S_arr[i] = 0.f;   // zero prefix only
    for (int i = tid; i < RK_LEN; i += 96) rk_sh[i] = (i < TNO) ? g_rk[i] : 0.f;
    __syncthreads();

    if (wid == 0) {
        // ---- serial warp ----
        const float W1 = rk_sh[500], W2 = rk_sh[499], W3 = rk_sh[498], W4 = rk_sh[497];
        const float wA0 = rk_sh[496 - lane];                       // sp0, d=5+lane
        const float wB0 = (lane == 0) ? 0.f : rk_sh[497 - lane];   // sp1, d=4+lane
        const float wX  = rk_sh[465];                              // sp1, d=36 (lane0 patch)

        // history at pair (t,t+1) entry: s1=s_{t-1}, s2=s_{t-2}, s3=s_{t-3}
        float s1 = 0.f, s2 = 0.f, s3 = 0.f;
        float preA  = An[0] + Far[0];
        float baseB = An[1] + Far[1];
        float thA = th_sh[0], thB = th_sh[1];
        int t = 0;

        #pragma unroll 1
        for (int ph = 0; ph < 128; ++ph) {
            #pragma unroll 2
            for (int i = 0; i < 8; ++i) {
                // step t
                float x0  = fmaf(s1, W1, preA);
                float sp0 = (x0 > thA) ? 1.f : 0.f;
                x_sh[t] = x0;
                float anC = An[t + 2], fbC = Far[t + 2];
                thA = th_sh[t + 2];
                // step t+1
                float preB = fmaf(s1, W2, fmaf(s2, W3, fmaf(s3, W4, baseB)));
                float x1  = fmaf(sp0, W1, preB);
                float sp1 = (x1 > thB) ? 1.f : 0.f;
                x_sh[t + 1] = x1;
                float anD = An[t + 3], fbD = Far[t + 3];
                thB = th_sh[t + 3];
                // single-chunk pair-combined scatter (lane-owned addresses)
                float* an = An + t + 5 + lane;
                an[0] += fmaf(sp0, wA0, sp1 * wB0);
                if (lane == 0) an[32] += sp1 * wX;
                // carries for next pair (step t+2: d=2 sp0, d=3 s1, d=4 s2)
                preA  = fmaf(sp0, W2, fmaf(s1, W3, fmaf(s2, W4, anC + fbC)));
                baseB = anD + fbD;
                s3 = s1; s2 = sp0; s1 = sp1;
                t += 2;
                asm volatile("" ::: "memory");   // compiler fence; same-warp MIO in-order
            }
            asm volatile("bar.sync 0, 96;" ::: "memory");
        }
    } else {
        // ---- helper warps ----
        const int q    = lane & 3;             // quarter of the 468-slot window
        const int tloc = lane >> 2;            // 0..7
        const int joff = 18 + (wid - 1) * 8 + tloc;   // j = 16*p + joff
        // register-resident weights: slot m = q*117+k covers tap d = 501-m;
        // valid far taps are d=37..501 <=> m<=464; mask m=465..467 (they alias
        // d=36..34, owned by warp0 — the R13 double-count bug).
        float wreg[117];
        #pragma unroll
        for (int k = 0; k < 117; ++k) {
            int m = q * 117 + k;
            wreg[k] = (m <= 464) ? rk_sh[m] : 0.f;
        }

        #pragma unroll 1
        for (int p = 0; p < 128; ++p) {
            // (a) redundant S materialization for block p-1 (bit-identical compare)
            if (p >= 1 && lane < 16) {
                int js = 16 * (p - 1) + lane;
                S_arr[SPAD + js] = (x_sh[js] > th_sh[js]) ? 1.f : 0.f;
            }
            asm volatile("" ::: "memory");      // order mat before gather (same warp)
            // (b) far gather for block at j = 16p + joff
            int j = 16 * p + joff;
            const float* sp = S_arr + (SPAD + j - 501) + q * 117;
            float a0 = 0.f, a1 = 0.f, a2 = 0.f;
            #pragma unroll
            for (int k = 0; k < 39; ++k) {
                a0 = fmaf(sp[3 * k],     wreg[3 * k],     a0);
                a1 = fmaf(sp[3 * k + 1], wreg[3 * k + 1], a1);
                a2 = fmaf(sp[3 * k + 2], wreg[3 * k + 2], a2);
            }
            float v = a0 + a1 + a2;
            v += __shfl_xor_sync(0xffffffffu, v, 1);
            v += __shfl_xor_sync(0xffffffffu, v, 2);
            if (q == 0 && j < T_TOT) Far[j] = v;   // single owner per j
            asm volatile("bar.sync 0, 96;" ::: "memory");
        }
    }

    // ---- parallel epilogue: P = sigmoid(x), S = (x > th) (bit-identical) ----
    float* Sout = out + b * T_TOT;
    float* Pout = out + B_TOT * T_TOT + b * T_TOT;
    for (int i = tid; i < T_TOT; i += 96) {
        float x = x_sh[i];
        Pout[i] = 1.0f / (1.0f + expf(-x));
        Sout[i] = (x > th_sh[i]) ? 1.f : 0.f;
    }
}

// ---------------- launch ----------------
extern "C" void kernel_launch(void* const* d_in, const int* in_sizes, int n_in,
                              void* d_out, int out_size) {
    const float* V  = (const float*)d_in[0];
    const float* D  = (const float*)d_in[1];
    const float* w1 = (const float*)d_in[2];
    const float* b1 = (const float*)d_in[3];
    const float* w2 = (const float*)d_in[4];
    const float* b2 = (const float*)d_in[5];
    const float* Wr = (const float*)d_in[6];
    float* out = (float*)d_out;

    k_pre<<<514, 256>>>(V, D, w1, b1, w2, b2, Wr);
    k_main<<<B_TOT, 96>>>(out);
}

// round 15
// speedup vs baseline: 2.4090x; 1.3074x over previous
#include <cuda_runtime.h>
#include <cstdint>
#include <math.h>

#define T_TOT 2048
#define B_TOT 64
#define TNO   501
#define DPI   3.141592653589793

// ---------------- scratch (no allocations allowed) ----------------
__device__ float g_rk[TNO];
__device__ float g_th[B_TOT * T_TOT];
__device__ float g_nn[B_TOT * T_TOT];

// ---------------- threefry2x32 (matches jax/_src/prng.py) ----------------
__host__ __device__ __forceinline__ constexpr uint32_t rotl32(uint32_t x, int r) {
    return (x << r) | (x >> (32 - r));
}

struct U2 { uint32_t a, b; };

__host__ __device__ __forceinline__ constexpr U2 tf2x32(uint32_t k0, uint32_t k1,
                                                        uint32_t x0, uint32_t x1) {
    uint32_t k2 = k0 ^ k1 ^ 0x1BD11BDAu;
    x0 += k0; x1 += k1;
#define TFR(r) { x0 += x1; x1 = rotl32(x1, (r)) ^ x0; }
    TFR(13) TFR(15) TFR(26) TFR(6)
    x0 += k1; x1 += k2 + 1u;
    TFR(17) TFR(29) TFR(16) TFR(24)
    x0 += k2; x1 += k0 + 2u;
    TFR(13) TFR(15) TFR(26) TFR(6)
    x0 += k0; x1 += k1 + 3u;
    TFR(17) TFR(29) TFR(16) TFR(24)
    x0 += k1; x1 += k2 + 4u;
    TFR(13) TFR(15) TFR(26) TFR(6)
    x0 += k2; x1 += k0 + 5u;
#undef TFR
    return U2{x0, x1};
}

// ---------------- compile-time key chain ----------------
struct SubTab { uint32_t v[2 * T_TOT]; };

constexpr SubTab make_subtab() {
    SubTab s{};
    uint32_t k0 = 0u, k1 = 42u;
    for (int t = 0; t < T_TOT; ++t) {
        U2 nk = tf2x32(k0, k1, 0u, 0u);
        U2 sb = tf2x32(k0, k1, 0u, 1u);
        s.v[2 * t]     = sb.a;
        s.v[2 * t + 1] = sb.b;
        k0 = nk.a; k1 = nk.b;
    }
    return s;
}

__device__ constexpr SubTab g_subtab = make_subtab();

// ---------------- double-float log (abs err ~1e-11 after cubic fix) ----------------
__device__ __forceinline__ void log_df(float v, float& rh, float& rl) {
    int iv = __float_as_int(v);
    int e = ((iv >> 23) & 0xFF) - 127;
    float m = __int_as_float((iv & 0x007FFFFF) | 0x3F800000);
    if (m > 1.4142135f) { m *= 0.5f; e += 1; }
    float num = m - 1.0f;                              // exact (Sterbenz)
    float dh = m + 1.0f;
    float bb = dh - m;
    float dl = (m - (dh - bb)) + (1.0f - bb);
    float q  = num / dh;
    float r  = fmaf(-q, dh, num);
    r        = fmaf(-q, dl, r);
    float zl = r / dh;                                 // z = q + zl (df)
    float z2 = q * q;
    float p = 0.0666666667f;
    p = fmaf(p, z2, 0.0769230769f);
    p = fmaf(p, z2, 0.0909090909f);
    p = fmaf(p, z2, 0.1111111111f);
    p = fmaf(p, z2, 0.1428571429f);
    p = fmaf(p, z2, 0.2f);
    p = fmaf(p, z2, 0.3333333333f);
    float hi = 2.0f * q;
    float corr = fmaf(zl, z2, zl);
    float lo = 2.0f * fmaf(q * z2, p, corr);
    float fe = (float)e;
    float eh = fe * 0.693145751953125f;
    float el = fe * 1.42860682e-06f;
    float s  = eh + hi;
    float b2 = s - eh;
    float er = (hi - b2) + (eh - (s - b2));
    rh = s;
    rl = er + el + lo;
}

// ---------------- compact fp64 log (abs err ~1e-15) ----------------
__device__ __forceinline__ double dlog(double v) {
    long long iv = __double_as_longlong(v);
    int e = (int)((iv >> 52) & 0x7FF) - 1023;
    double m = __longlong_as_double((iv & 0x000FFFFFFFFFFFFFULL) | 0x3FF0000000000000ULL);
    if (m > 1.4142135623730951) { m *= 0.5; e += 1; }
    double z  = (m - 1.0) / (m + 1.0);
    double z2 = z * z;
    double p = 1.0 / 21.0;
    p = fma(p, z2, 1.0 / 19.0);
    p = fma(p, z2, 1.0 / 17.0);
    p = fma(p, z2, 1.0 / 15.0);
    p = fma(p, z2, 1.0 / 13.0);
    p = fma(p, z2, 1.0 / 11.0);
    p = fma(p, z2, 1.0 / 9.0);
    p = fma(p, z2, 1.0 / 7.0);
    p = fma(p, z2, 1.0 / 5.0);
    p = fma(p, z2, 1.0 / 3.0);
    double inner = fma(2.0 * z * z2, p, 2.0 * z);
    return fma((double)e, 0.6931471805599453, inner);
}

__device__ __forceinline__ float floor_f32_of_double(double thd) {
    float T = (float)thd;
    if ((double)T > thd) {
        int ib = __float_as_int(T);
        if (T > 0.f)      ib -= 1;
        else if (T < 0.f) ib += 1;
        else              ib = (int)0x80000001;
        T = __int_as_float(ib);
    }
    return T;
}

// ---------------- fused precompute ----------------
// blocks 0..511: thresholds + nn logits (unchanged from passing R14)
// blocks 512..574: rk, one WARP per t — each lane computes one (t,i) basis
//   value with the SAME fp64 expressions as before (identical doubles), lane 0
//   replays the exact serial f32 fmaf reduction => g_rk is bit-identical, but
//   the fp64 cos/log work spreads over 63 SMs instead of 2 (kills the ~28us tail).
__global__ void k_pre(const float* __restrict__ V, const float* __restrict__ D,
                      const float* __restrict__ w1, const float* __restrict__ b1,
                      const float* __restrict__ w2, const float* __restrict__ b2,
                      const float* __restrict__ Wr) {
    if (blockIdx.x >= 512) {
        __shared__ float shb[8][30];
        int widL = threadIdx.x >> 5;
        int lane = threadIdx.x & 31;
        int t = (blockIdx.x - 512) * 8 + widL;
        if (t >= TNO) return;
        if (lane < 30) {
            double raw = 7.5 * log(((double)t + 1.0) + 1e-7);
            double phi = (0.5 * DPI) * (double)lane;
            double bv;
            if (raw < phi - DPI || raw > phi + DPI) bv = 0.0;
            else bv = 0.5 * cos(raw - phi) + 0.5;
            shb[widL][lane] = (float)bv;
        }
        __syncwarp();
        if (lane == 0) {
            float acc = 0.f;
            for (int i = 0; i < 30; ++i)
                acc = fmaf(shb[widL][i], Wr[i], acc);   // exact serial order
            g_rk[500 - t] = acc;   // jnp.flip
        }
        return;
    }

    int tid = blockIdx.x * 256 + threadIdx.x;   // b*T + t layout
    int b = tid >> 11;
    int t = tid & (T_TOT - 1);

    uint32_t s0 = g_subtab.v[2 * t];
    uint32_t s1 = g_subtab.v[2 * t + 1];
    U2 o = tf2x32(s0, s1, 0u, (uint32_t)b);
    uint32_t bits = o.a ^ o.b;
    uint32_t kb = bits >> 9;                       // u = kb * 2^-23, exact
    float th;
    if (kb == 0u) {
        th = __int_as_float(0xFF800000);           // -inf: always spike
    } else {
        float u = __uint_as_float(kb | 0x3f800000u) - 1.0f;
        float w = 1.0f - u;                        // exact
        float luh, lul, lwh, lwl;
        log_df(u, luh, lul);
        log_df(w, lwh, lwl);
        float s  = luh - lwh;
        float bb = s - luh;
        float er = (-lwh - bb) + (luh - (s - bb));
        float lo = er + (lul - lwl);
        float H = s + lo;
        float L = lo - (H - s);
        if (L < 0.0f) {
            int ib = __float_as_int(H);
            if (H > 0.0f)      ib -= 1;
            else if (H < 0.0f) ib += 1;
            else               ib = (int)0x80000001;
            H = __int_as_float(ib);
        }
        float dist = (s - H) + lo;
        int ih = __float_as_int(H);
        float Hn = __int_as_float((H > 0.f) ? ih + 1 : ((H < 0.f) ? ih - 1 : 1));
        float width = Hn - H;
        float eps = 2e-10f + 2e-11f * fabsf(H);
        if (!(dist > eps && (width - dist) > eps)) {
            double ud = (double)u;
            double thd = dlog(ud / (1.0 - ud));
            H = floor_f32_of_double(thd);
        }
        th = H;
    }
    g_th[tid] = th;

    float v = V[tid], d = D[tid];
    float acc = 0.f;
    #pragma unroll
    for (int h = 0; h < 5; ++h) {
        float s = fmaf(w1[2 * h + 1], d, w1[2 * h + 0] * v) + b1[h];
        float hh = tanhf(s);
        acc = (h == 0) ? w2[0] * hh : fmaf(w2[h], hh, acc);
    }
    g_nn[tid] = acc + b2[0];
}

// ---------------- autoregressive loop: 5 warps per batch, 16-step phases ----------------
// wid 2 (private SMSP2): serial chain; d=1..4 regs, d=5..35 single-chunk scatter
//   (sp0 lane31 weight masked — d=36 moved to helpers).
// wids 0,1,3,4: helpers. Per phase p: (a) each redundantly materializes S for
//   block p-1 (reads only its own writes — same-warp MIO in-order), (b) gathers
//   Far[j] = sum_{d=36..501} S[j-d]*rk[501-d] (slots m<=465; higher m masked —
//   they alias warp-owned taps, the R13 bug class), 8 lanes x 59 taps per
//   target, register weights, 3-level shfl reduce, single-owner write.
#define AN_LEN 2112
#define FB_LEN 2080
#define TH_LEN 2056
#define SPAD   512
#define S_LEN  (SPAD + T_TOT)
#define RK_LEN 512
#define NTHR   160

__global__ void __launch_bounds__(NTHR, 1) k_main(float* __restrict__ out) {
    __shared__ float An[AN_LEN];      // init = nn (j<2048) else 0; near accum d<=35
    __shared__ float Far[FB_LEN];     // d>=36 background (helper-gathered)
    __shared__ float th_sh[TH_LEN];
    __shared__ float x_sh[T_TOT];
    __shared__ float S_arr[S_LEN];    // 512-zero prefix, then spikes
    __shared__ float rk_sh[RK_LEN];

    const int b = blockIdx.x;
    const int tid = threadIdx.x;
    const int wid = tid >> 5;
    const int lane = tid & 31;

    // ---- init ----
    {
        const float4* nn4 = reinterpret_cast<const float4*>(g_nn + b * T_TOT);
        const float4* th4 = reinterpret_cast<const float4*>(g_th + b * T_TOT);
        float4* An4 = reinterpret_cast<float4*>(An);
        float4* Th4 = reinterpret_cast<float4*>(th_sh);
        for (int i = tid; i < T_TOT / 4; i += NTHR) { An4[i] = nn4[i]; Th4[i] = th4[i]; }
    }
    for (int i = T_TOT + tid; i < AN_LEN; i += NTHR) An[i] = 0.f;
    for (int i = T_TOT + tid; i < TH_LEN; i += NTHR) th_sh[i] = 0.f;
    for (int i = tid; i < FB_LEN; i += NTHR) Far[i] = 0.f;
    for (int i = tid; i < SPAD; i += NTHR) S_arr[i] = 0.f;   // zero prefix only
    for (int i = tid; i < RK_LEN; i += NTHR) rk_sh[i] = (i < TNO) ? g_rk[i] : 0.f;
    __syncthreads();

    if (wid == 2) {
        // ---- serial warp (private SMSP) ----
        const float W1 = rk_sh[500], W2 = rk_sh[499], W3 = rk_sh[498], W4 = rk_sh[497];
        const float wA0 = (lane == 31) ? 0.f : rk_sh[496 - lane];  // sp0, d=5+lane (d=36 -> helpers)
        const float wB0 = (lane == 0) ? 0.f : rk_sh[497 - lane];   // sp1, d=4+lane (d=4 in regs)

        // history at pair (t,t+1) entry: s1=s_{t-1}, s2=s_{t-2}, s3=s_{t-3}
        float s1 = 0.f, s2 = 0.f, s3 = 0.f;
        float preA  = An[0] + Far[0];
        float baseB = An[1] + Far[1];
        float thA = th_sh[0], thB = th_sh[1];
        int t = 0;

        #pragma unroll 1
        for (int ph = 0; ph < 128; ++ph) {
            #pragma unroll 2
            for (int i = 0; i < 8; ++i) {
                // step t
                float x0  = fmaf(s1, W1, preA);
                float sp0 = (x0 > thA) ? 1.f : 0.f;
                x_sh[t] = x0;
                float anC = An[t + 2], fbC = Far[t + 2];
                thA = th_sh[t + 2];
                // step t+1
                float preB = fmaf(s1, W2, fmaf(s2, W3, fmaf(s3, W4, baseB)));
                float x1  = fmaf(sp0, W1, preB);
                float sp1 = (x1 > thB) ? 1.f : 0.f;
                x_sh[t + 1] = x1;
                float anD = An[t + 3], fbD = Far[t + 3];
                thB = th_sh[t + 3];
                // single-chunk pair-combined scatter (lane-owned addresses)
                float* an = An + t + 5 + lane;
                an[0] += fmaf(sp0, wA0, sp1 * wB0);
                // carries for next pair (step t+2: d=2 sp0, d=3 s1, d=4 s2)
                preA  = fmaf(sp0, W2, fmaf(s1, W3, fmaf(s2, W4, anC + fbC)));
                baseB = anD + fbD;
                s3 = s1; s2 = sp0; s1 = sp1;
                t += 2;
                asm volatile("" ::: "memory");   // compiler fence; same-warp MIO in-order
            }
            asm volatile("bar.sync 0, 160;" ::: "memory");
        }
    } else {
        // ---- helper warps (4) ----
        const int h    = (wid < 2) ? wid : wid - 1;   // 0..3
        const int q    = lane & 7;             // eighth of the 472-slot window
        const int tloc = lane >> 3;            // 0..3
        const int joff = 18 + h * 4 + tloc;    // j = 16*p + joff, 16 distinct targets
        // slots m = q*59+k (k<60; wreg[59]=0 pad). Tap d = 501-m; valid far taps
        // d>=36 <=> m<=465; mask m>465 (alias warp-owned taps d<36).
        float wreg[60];
        #pragma unroll
        for (int k = 0; k < 59; ++k) {
            int m = q * 59 + k;
            wreg[k] = (m <= 465) ? rk_sh[m] : 0.f;
        }
        wreg[59] = 0.f;

        #pragma unroll 1
        for (int p = 0; p < 128; ++p) {
            // (a) redundant S materialization for block p-1 (bit-identical compare)
            if (p >= 1 && lane < 16) {
                int js = 16 * (p - 1) + lane;
                S_arr[SPAD + js] = (x_sh[js] > th_sh[js]) ? 1.f : 0.f;
            }
            asm volatile("" ::: "memory");      // order mat before gather (same warp)
            // (b) far gather for target j = 16p + joff
            int j = 16 * p + joff;
            const float* sp = S_arr + (SPAD + j - 501) + q * 59;
            float a0 = 0.f, a1 = 0.f, a2 = 0.f;
            #pragma unroll
            for (int k = 0; k < 20; ++k) {
                a0 = fmaf(sp[3 * k],     wreg[3 * k],     a0);
                a1 = fmaf(sp[3 * k + 1], wreg[3 * k + 1], a1);
                a2 = fmaf(sp[3 * k + 2], wreg[3 * k + 2], a2);
            }
            float v = a0 + a1 + a2;
            v += __shfl_xor_sync(0xffffffffu, v, 1);
            v += __shfl_xor_sync(0xffffffffu, v, 2);
            v += __shfl_xor_sync(0xffffffffu, v, 4);
            if (q == 0) Far[j] = v;             // single owner per j (j<=2065<FB_LEN)
            asm volatile("bar.sync 0, 160;" ::: "memory");
        }
    }

    // ---- parallel epilogue: P = sigmoid(x), S = (x > th) (bit-identical) ----
    float* Sout = out + b * T_TOT;
    float* Pout = out + B_TOT * T_TOT + b * T_TOT;
    for (int i = tid; i < T_TOT; i += NTHR) {
        float x = x_sh[i];
        Pout[i] = 1.0f / (1.0f + expf(-x));
        Sout[i] = (x > th_sh[i]) ? 1.f : 0.f;
    }
}

// ---------------- launch ----------------
extern "C" void kernel_launch(void* const* d_in, const int* in_sizes, int n_in,
                              void* d_out, int out_size) {
    const float* V  = (const float*)d_in[0];
    const float* D  = (const float*)d_in[1];
    const float* w1 = (const float*)d_in[2];
    const float* b1 = (const float*)d_in[3];
    const float* w2 = (const float*)d_in[4];
    const float* b2 = (const float*)d_in[5];
    const float* Wr = (const float*)d_in[6];
    float* out = (float*)d_out;

    k_pre<<<575, 256>>>(V, D, w1, b1, w2, b2, Wr);
    k_main<<<B_TOT, NTHR>>>(out);
}

// round 16
// speedup vs baseline: 2.4101x; 1.0004x over previous
#include <cuda_runtime.h>
#include <cstdint>
#include <math.h>

#define T_TOT 2048
#define B_TOT 64
#define TNO   501
#define DPI   3.141592653589793

// ---------------- scratch (no allocations allowed) ----------------
__device__ float g_rk[TNO];
__device__ float g_th[B_TOT * T_TOT];
__device__ float g_nn[B_TOT * T_TOT];

// ---------------- threefry2x32 (matches jax/_src/prng.py) ----------------
__host__ __device__ __forceinline__ constexpr uint32_t rotl32(uint32_t x, int r) {
    return (x << r) | (x >> (32 - r));
}

struct U2 { uint32_t a, b; };

__host__ __device__ __forceinline__ constexpr U2 tf2x32(uint32_t k0, uint32_t k1,
                                                        uint32_t x0, uint32_t x1) {
    uint32_t k2 = k0 ^ k1 ^ 0x1BD11BDAu;
    x0 += k0; x1 += k1;
#define TFR(r) { x0 += x1; x1 = rotl32(x1, (r)) ^ x0; }
    TFR(13) TFR(15) TFR(26) TFR(6)
    x0 += k1; x1 += k2 + 1u;
    TFR(17) TFR(29) TFR(16) TFR(24)
    x0 += k2; x1 += k0 + 2u;
    TFR(13) TFR(15) TFR(26) TFR(6)
    x0 += k0; x1 += k1 + 3u;
    TFR(17) TFR(29) TFR(16) TFR(24)
    x0 += k1; x1 += k2 + 4u;
    TFR(13) TFR(15) TFR(26) TFR(6)
    x0 += k2; x1 += k0 + 5u;
#undef TFR
    return U2{x0, x1};
}

// ---------------- compile-time key chain ----------------
struct SubTab { uint32_t v[2 * T_TOT]; };

constexpr SubTab make_subtab() {
    SubTab s{};
    uint32_t k0 = 0u, k1 = 42u;
    for (int t = 0; t < T_TOT; ++t) {
        U2 nk = tf2x32(k0, k1, 0u, 0u);
        U2 sb = tf2x32(k0, k1, 0u, 1u);
        s.v[2 * t]     = sb.a;
        s.v[2 * t + 1] = sb.b;
        k0 = nk.a; k1 = nk.b;
    }
    return s;
}

__device__ constexpr SubTab g_subtab = make_subtab();

// FSET: float compare producing 1.0f/0.0f in ONE 4-cyc FMA-pipe op
// (replaces FSETP(13, pred-as-guard) + FSEL — bit-identical result).
__device__ __forceinline__ float fset_gt(float a, float b) {
    float d;
    asm("set.gt.f32.f32 %0, %1, %2;" : "=f"(d) : "f"(a), "f"(b));
    return d;
}

// ---------------- double-float log (abs err ~1e-11 after cubic fix) ----------------
__device__ __forceinline__ void log_df(float v, float& rh, float& rl) {
    int iv = __float_as_int(v);
    int e = ((iv >> 23) & 0xFF) - 127;
    float m = __int_as_float((iv & 0x007FFFFF) | 0x3F800000);
    if (m > 1.4142135f) { m *= 0.5f; e += 1; }
    float num = m - 1.0f;                              // exact (Sterbenz)
    float dh = m + 1.0f;
    float bb = dh - m;
    float dl = (m - (dh - bb)) + (1.0f - bb);
    float q  = num / dh;
    float r  = fmaf(-q, dh, num);
    r        = fmaf(-q, dl, r);
    float zl = r / dh;                                 // z = q + zl (df)
    float z2 = q * q;
    float p = 0.0666666667f;
    p = fmaf(p, z2, 0.0769230769f);
    p = fmaf(p, z2, 0.0909090909f);
    p = fmaf(p, z2, 0.1111111111f);
    p = fmaf(p, z2, 0.1428571429f);
    p = fmaf(p, z2, 0.2f);
    p = fmaf(p, z2, 0.3333333333f);
    float hi = 2.0f * q;
    float corr = fmaf(zl, z2, zl);
    float lo = 2.0f * fmaf(q * z2, p, corr);
    float fe = (float)e;
    float eh = fe * 0.693145751953125f;
    float el = fe * 1.42860682e-06f;
    float s  = eh + hi;
    float b2 = s - eh;
    float er = (hi - b2) + (eh - (s - b2));
    rh = s;
    rl = er + el + lo;
}

// ---------------- compact fp64 log (abs err ~1e-15) ----------------
__device__ __forceinline__ double dlog(double v) {
    long long iv = __double_as_longlong(v);
    int e = (int)((iv >> 52) & 0x7FF) - 1023;
    double m = __longlong_as_double((iv & 0x000FFFFFFFFFFFFFULL) | 0x3FF0000000000000ULL);
    if (m > 1.4142135623730951) { m *= 0.5; e += 1; }
    double z  = (m - 1.0) / (m + 1.0);
    double z2 = z * z;
    double p = 1.0 / 21.0;
    p = fma(p, z2, 1.0 / 19.0);
    p = fma(p, z2, 1.0 / 17.0);
    p = fma(p, z2, 1.0 / 15.0);
    p = fma(p, z2, 1.0 / 13.0);
    p = fma(p, z2, 1.0 / 11.0);
    p = fma(p, z2, 1.0 / 9.0);
    p = fma(p, z2, 1.0 / 7.0);
    p = fma(p, z2, 1.0 / 5.0);
    p = fma(p, z2, 1.0 / 3.0);
    double inner = fma(2.0 * z * z2, p, 2.0 * z);
    return fma((double)e, 0.6931471805599453, inner);
}

__device__ __forceinline__ float floor_f32_of_double(double thd) {
    float T = (float)thd;
    if ((double)T > thd) {
        int ib = __float_as_int(T);
        if (T > 0.f)      ib -= 1;
        else if (T < 0.f) ib += 1;
        else              ib = (int)0x80000001;
        T = __int_as_float(ib);
    }
    return T;
}

// ---------------- fused precompute (unchanged from passing R15) ----------------
__global__ void k_pre(const float* __restrict__ V, const float* __restrict__ D,
                      const float* __restrict__ w1, const float* __restrict__ b1,
                      const float* __restrict__ w2, const float* __restrict__ b2,
                      const float* __restrict__ Wr) {
    if (blockIdx.x >= 512) {
        __shared__ float shb[8][30];
        int widL = threadIdx.x >> 5;
        int lane = threadIdx.x & 31;
        int t = (blockIdx.x - 512) * 8 + widL;
        if (t >= TNO) return;
        if (lane < 30) {
            double raw = 7.5 * log(((double)t + 1.0) + 1e-7);
            double phi = (0.5 * DPI) * (double)lane;
            double bv;
            if (raw < phi - DPI || raw > phi + DPI) bv = 0.0;
            else bv = 0.5 * cos(raw - phi) + 0.5;
            shb[widL][lane] = (float)bv;
        }
        __syncwarp();
        if (lane == 0) {
            float acc = 0.f;
            for (int i = 0; i < 30; ++i)
                acc = fmaf(shb[widL][i], Wr[i], acc);   // exact serial order
            g_rk[500 - t] = acc;   // jnp.flip
        }
        return;
    }

    int tid = blockIdx.x * 256 + threadIdx.x;   // b*T + t layout
    int b = tid >> 11;
    int t = tid & (T_TOT - 1);

    uint32_t s0 = g_subtab.v[2 * t];
    uint32_t s1 = g_subtab.v[2 * t + 1];
    U2 o = tf2x32(s0, s1, 0u, (uint32_t)b);
    uint32_t bits = o.a ^ o.b;
    uint32_t kb = bits >> 9;                       // u = kb * 2^-23, exact
    float th;
    if (kb == 0u) {
        th = __int_as_float(0xFF800000);           // -inf: always spike
    } else {
        float u = __uint_as_float(kb | 0x3f800000u) - 1.0f;
        float w = 1.0f - u;                        // exact
        float luh, lul, lwh, lwl;
        log_df(u, luh, lul);
        log_df(w, lwh, lwl);
        float s  = luh - lwh;
        float bb = s - luh;
        float er = (-lwh - bb) + (luh - (s - bb));
        float lo = er + (lul - lwl);
        float H = s + lo;
        float L = lo - (H - s);
        if (L < 0.0f) {
            int ib = __float_as_int(H);
            if (H > 0.0f)      ib -= 1;
            else if (H < 0.0f) ib += 1;
            else               ib = (int)0x80000001;
            H = __int_as_float(ib);
        }
        float dist = (s - H) + lo;
        int ih = __float_as_int(H);
        float Hn = __int_as_float((H > 0.f) ? ih + 1 : ((H < 0.f) ? ih - 1 : 1));
        float width = Hn - H;
        float eps = 2e-10f + 2e-11f * fabsf(H);
        if (!(dist > eps && (width - dist) > eps)) {
            double ud = (double)u;
            double thd = dlog(ud / (1.0 - ud));
            H = floor_f32_of_double(thd);
        }
        th = H;
    }
    g_th[tid] = th;

    float v = V[tid], d = D[tid];
    float acc = 0.f;
    #pragma unroll
    for (int h = 0; h < 5; ++h) {
        float s = fmaf(w1[2 * h + 1], d, w1[2 * h + 0] * v) + b1[h];
        float hh = tanhf(s);
        acc = (h == 0) ? w2[0] * hh : fmaf(w2[h], hh, acc);
    }
    g_nn[tid] = acc + b2[0];
}

// ---------------- autoregressive loop: 5 warps per batch, 16-step phases ----------------
// Identical structure to passing R15; the ONLY change is warp0's spike decision:
// FSET (set.gt.f32.f32, 1 op, lat 4) replaces FSETP(13)+FSEL(4) — bit-identical
// value, cuts the serial chain ~42 -> ~18 cyc/pair.
#define AN_LEN 2112
#define FB_LEN 2080
#define TH_LEN 2056
#define SPAD   512
#define S_LEN  (SPAD + T_TOT)
#define RK_LEN 512
#define NTHR   160

__global__ void __launch_bounds__(NTHR, 1) k_main(float* __restrict__ out) {
    __shared__ float An[AN_LEN];      // init = nn (j<2048) else 0; near accum d<=35
    __shared__ float Far[FB_LEN];     // d>=36 background (helper-gathered)
    __shared__ float th_sh[TH_LEN];
    __shared__ float x_sh[T_TOT];
    __shared__ float S_arr[S_LEN];    // 512-zero prefix, then spikes
    __shared__ float rk_sh[RK_LEN];

    const int b = blockIdx.x;
    const int tid = threadIdx.x;
    const int wid = tid >> 5;
    const int lane = tid & 31;

    // ---- init ----
    {
        const float4* nn4 = reinterpret_cast<const float4*>(g_nn + b * T_TOT);
        const float4* th4 = reinterpret_cast<const float4*>(g_th + b * T_TOT);
        float4* An4 = reinterpret_cast<float4*>(An);
        float4* Th4 = reinterpret_cast<float4*>(th_sh);
        for (int i = tid; i < T_TOT / 4; i += NTHR) { An4[i] = nn4[i]; Th4[i] = th4[i]; }
    }
    for (int i = T_TOT + tid; i < AN_LEN; i += NTHR) An[i] = 0.f;
    for (int i = T_TOT + tid; i < TH_LEN; i += NTHR) th_sh[i] = 0.f;
    for (int i = tid; i < FB_LEN; i += NTHR) Far[i] = 0.f;
    for (int i = tid; i < SPAD; i += NTHR) S_arr[i] = 0.f;   // zero prefix only
    for (int i = tid; i < RK_LEN; i += NTHR) rk_sh[i] = (i < TNO) ? g_rk[i] : 0.f;
    __syncthreads();

    if (wid == 2) {
        // ---- serial warp (private SMSP) ----
        const float W1 = rk_sh[500], W2 = rk_sh[499], W3 = rk_sh[498], W4 = rk_sh[497];
        const float wA0 = (lane == 31) ? 0.f : rk_sh[496 - lane];  // sp0, d=5+lane (d=36 -> helpers)
        const float wB0 = (lane == 0) ? 0.f : rk_sh[497 - lane];   // sp1, d=4+lane (d=4 in regs)

        // history at pair (t,t+1) entry: s1=s_{t-1}, s2=s_{t-2}, s3=s_{t-3}
        float s1 = 0.f, s2 = 0.f, s3 = 0.f;
        float preA  = An[0] + Far[0];
        float baseB = An[1] + Far[1];
        float thA = th_sh[0], thB = th_sh[1];
        int t = 0;

        #pragma unroll 1
        for (int ph = 0; ph < 128; ++ph) {
            #pragma unroll 2
            for (int i = 0; i < 8; ++i) {
                // step t
                float x0  = fmaf(s1, W1, preA);
                float sp0 = fset_gt(x0, thA);          // FSET: 1 op, lat 4
                x_sh[t] = x0;
                float anC = An[t + 2], fbC = Far[t + 2];
                thA = th_sh[t + 2];
                // step t+1
                float preB = fmaf(s1, W2, fmaf(s2, W3, fmaf(s3, W4, baseB)));
                float x1  = fmaf(sp0, W1, preB);
                float sp1 = fset_gt(x1, thB);          // FSET: 1 op, lat 4
                x_sh[t + 1] = x1;
                float anD = An[t + 3], fbD = Far[t + 3];
                thB = th_sh[t + 3];
                // single-chunk pair-combined scatter (lane-owned addresses)
                float* an = An + t + 5 + lane;
                an[0] += fmaf(sp0, wA0, sp1 * wB0);
                // carries for next pair (step t+2: d=2 sp0, d=3 s1, d=4 s2)
                preA  = fmaf(sp0, W2, fmaf(s1, W3, fmaf(s2, W4, anC + fbC)));
                baseB = anD + fbD;
                s3 = s1; s2 = sp0; s1 = sp1;
                t += 2;
                asm volatile("" ::: "memory");   // compiler fence; same-warp MIO in-order
            }
            asm volatile("bar.sync 0, 160;" ::: "memory");
        }
    } else {
        // ---- helper warps (4) ----
        const int h    = (wid < 2) ? wid : wid - 1;   // 0..3
        const int q    = lane & 7;             // eighth of the 472-slot window
        const int tloc = lane >> 3;            // 0..3
        const int joff = 18 + h * 4 + tloc;    // j = 16*p + joff, 16 distinct targets
        // slots m = q*59+k (k<60; wreg[59]=0 pad). Tap d = 501-m; valid far taps
        // d>=36 <=> m<=465; mask m>465 (alias warp-owned taps d<36).
        float wreg[60];
        #pragma unroll
        for (int k = 0; k < 59; ++k) {
            int m = q * 59 + k;
            wreg[k] = (m <= 465) ? rk_sh[m] : 0.f;
        }
        wreg[59] = 0.f;

        #pragma unroll 1
        for (int p = 0; p < 128; ++p) {
            // (a) redundant S materialization for block p-1 (bit-identical compare)
            if (p >= 1 && lane < 16) {
                int js = 16 * (p - 1) + lane;
                S_arr[SPAD + js] = (x_sh[js] > th_sh[js]) ? 1.f : 0.f;
            }
            asm volatile("" ::: "memory");      // order mat before gather (same warp)
            // (b) far gather for target j = 16p + joff
            int j = 16 * p + joff;
            const float* sp = S_arr + (SPAD + j - 501) + q * 59;
            float a0 = 0.f, a1 = 0.f, a2 = 0.f;
            #pragma unroll
            for (int k = 0; k < 20; ++k) {
                a0 = fmaf(sp[3 * k],     wreg[3 * k],     a0);
                a1 = fmaf(sp[3 * k + 1], wreg[3 * k + 1], a1);
                a2 = fmaf(sp[3 * k + 2], wreg[3 * k + 2], a2);
            }
            float v = a0 + a1 + a2;
            v += __shfl_xor_sync(0xffffffffu, v, 1);
            v += __shfl_xor_sync(0xffffffffu, v, 2);
            v += __shfl_xor_sync(0xffffffffu, v, 4);
            if (q == 0) Far[j] = v;             // single owner per j (j<=2065<FB_LEN)
            asm volatile("bar.sync 0, 160;" ::: "memory");
        }
    }

    // ---- parallel epilogue: P = sigmoid(x), S = (x > th) (bit-identical) ----
    float* Sout = out + b * T_TOT;
    float* Pout = out + B_TOT * T_TOT + b * T_TOT;
    for (int i = tid; i < T_TOT; i += NTHR) {
        float x = x_sh[i];
        Pout[i] = 1.0f / (1.0f + expf(-x));
        Sout[i] = (x > th_sh[i]) ? 1.f : 0.f;
    }
}

// ---------------- launch ----------------
extern "C" void kernel_launch(void* const* d_in, const int* in_sizes, int n_in,
                              void* d_out, int out_size) {
    const float* V  = (const float*)d_in[0];
    const float* D  = (const float*)d_in[1];
    const float* w1 = (const float*)d_in[2];
    const float* b1 = (const float*)d_in[3];
    const float* w2 = (const float*)d_in[4];
    const float* b2 = (const float*)d_in[5];
    const float* Wr = (const float*)d_in[6];
    float* out = (float*)d_out;

    k_pre<<<575, 256>>>(V, D, w1, b1, w2, b2, Wr);
    k_main<<<B_TOT, NTHR>>>(out);
}